// round 10
// baseline (speedup 1.0000x reference)
#include <cuda_runtime.h>
#include <cstdint>

#define NN 50000
#define NE 800000
#define C  96
#define TM 128
#define NTILES 391            // ceil(NN/TM)
#define NPAIRS 196            // ceil(NTILES/2)
#define NB 148                // persistent blocks (co-resident, 1/SM)
#define NT 512
#define GSZ (NB * NT)
#define CHUNK 338             // ceil(NN/NB)

// ---------------- scratch (device globals; no allocation allowed) ----------
__device__ float g_H[NN * C];
__device__ float g_P[NN * C];
__device__ int   g_cnt[NN];
__device__ int   g_cursor[NN];
__device__ int   g_rowptr[NN + 1];
__device__ int2  g_edge[NE];          // (src, bits(w)) grouped by dst
__device__ int   g_bsum[NB];
__device__ unsigned g_bar_count;
__device__ unsigned g_bar_gen;

// ---------------- software grid barrier (all NB blocks co-resident) --------
__device__ __forceinline__ void grid_barrier() {
    __syncthreads();
    if (threadIdx.x == 0) {
        unsigned gen = *(volatile unsigned*)&g_bar_gen;
        __threadfence();
        if (atomicAdd(&g_bar_count, 1u) == NB - 1) {
            g_bar_count = 0u;
            __threadfence();
            *(volatile unsigned*)&g_bar_gen = gen + 1u;
        } else {
            while (*(volatile unsigned*)&g_bar_gen == gen) __nanosleep(64);
        }
    }
    __syncthreads();
}

// ---------------- GEMM tile (256 threads per tile, packed f32x2 math) ------
// ltid: ng = ltid>>3 (4 nodes), cg = ltid&7 (12 channels = 6 f32x2 pairs).
// Register-prefetched double buffering of W/X chunks. Ws shared between
// halves; Xs per-half.
__device__ __forceinline__ void gemm_tile(const float* __restrict__ in,
                                          const float* __restrict__ W,
                                          float* __restrict__ out,
                                          int cin, int tile,
                                          float (*Xs)[33], float (*Ws)[96]) {
    const int tid = threadIdx.x;        // 0..511
    const int ltid = tid & 255;
    const int cg = ltid & 7;
    const int ng = ltid >> 3;
    const int node0 = tile * TM;

    // X-load geometry (per half, 4 float4 per thread per chunk)
    int xr[4], xkq[4];
    const float* xbase[4];
#pragma unroll
    for (int i = 0; i < 4; i++) {
        int li = ltid + i * 256;
        xr[i] = li >> 3; xkq[i] = li & 7;
        int nd = node0 + xr[i];
        xbase[i] = (nd < NN) ? in + (size_t)nd * cin : nullptr;
    }
    // W-load geometry (half 0 only, 3 float4 per thread per chunk)
    int wr[3], wcq[3];
#pragma unroll
    for (int i = 0; i < 3; i++) {
        int li = tid + i * 256;
        wr[i] = li / 24; wcq[i] = li % 24;
    }

    // 4 nodes x 6 channel-pairs, packed f32x2 accumulators
    unsigned long long acc2[4][6];
#pragma unroll
    for (int i = 0; i < 4; i++)
#pragma unroll
        for (int j = 0; j < 6; j++) acc2[i][j] = 0ull;

    const int nkc = cin >> 5;

    // prologue: prefetch chunk 0
    float4 px[4], pw[3];
#pragma unroll
    for (int i = 0; i < 4; i++)
        px[i] = xbase[i] ? __ldcg((const float4*)(xbase[i]) + xkq[i])
                         : make_float4(0.f, 0.f, 0.f, 0.f);
    if (tid < 256) {
#pragma unroll
        for (int i = 0; i < 3; i++)
            pw[i] = ((const float4*)(W + (size_t)wr[i] * 96))[wcq[i]];
    }

    for (int kc = 0; kc < nkc; kc++) {
        // commit prefetched chunk kc to smem
        if (tid < 256) {
#pragma unroll
            for (int i = 0; i < 3; i++)
                *(float4*)&Ws[wr[i]][wcq[i] * 4] = pw[i];
        }
#pragma unroll
        for (int i = 0; i < 4; i++) {
            Xs[xr[i]][xkq[i] * 4 + 0] = px[i].x;
            Xs[xr[i]][xkq[i] * 4 + 1] = px[i].y;
            Xs[xr[i]][xkq[i] * 4 + 2] = px[i].z;
            Xs[xr[i]][xkq[i] * 4 + 3] = px[i].w;
        }
        __syncthreads();

        // prefetch chunk kc+1 (LDGs overlap with compute below)
        if (kc + 1 < nkc) {
            const int koff = (kc + 1) * 32;
#pragma unroll
            for (int i = 0; i < 4; i++)
                px[i] = xbase[i] ? __ldcg((const float4*)(xbase[i] + koff) + xkq[i])
                                 : make_float4(0.f, 0.f, 0.f, 0.f);
            if (tid < 256) {
#pragma unroll
                for (int i = 0; i < 3; i++)
                    pw[i] = ((const float4*)(W + (size_t)(koff + wr[i]) * 96))[wcq[i]];
            }
        }

#pragma unroll
        for (int k = 0; k < 32; k++) {
            // 6 channel pairs from Ws (8-byte aligned: cg*12 floats = 48B)
            const unsigned long long* wp =
                (const unsigned long long*)&Ws[k][cg * 12];
            unsigned long long w[6];
#pragma unroll
            for (int j = 0; j < 6; j++) w[j] = wp[j];
#pragma unroll
            for (int i = 0; i < 4; i++) {
                unsigned xb = __float_as_uint(Xs[ng * 4 + i][k]);
                unsigned long long xx;
                asm("mov.b64 %0, {%1, %1};" : "=l"(xx) : "r"(xb));
#pragma unroll
                for (int j = 0; j < 6; j++)
                    asm("fma.rn.f32x2 %0, %1, %2, %0;"
                        : "+l"(acc2[i][j]) : "l"(xx), "l"(w[j]));
            }
        }
        __syncthreads();
    }

#pragma unroll
    for (int i = 0; i < 4; i++) {
        int nd = node0 + ng * 4 + i;
        if (nd < NN) {
            unsigned long long* o =
                (unsigned long long*)(out + (size_t)nd * 96 + cg * 12);
#pragma unroll
            for (int j = 0; j < 6; j++) o[j] = acc2[i][j];
        }
    }
}

// ---------------- gather phase: 4 nodes per warp (8 lanes each) -------------
// sublane covers float4 cols {sub, sub+8, sub+16}; 4 independent edge chains
// per warp -> 4x MLP on the edge->row dependency.
__device__ __forceinline__ void gather_phase(const float* __restrict__ h,
                                             const float* __restrict__ b,
                                             float* __restrict__ out, int relu) {
    const int lane = threadIdx.x & 31;
    const int sub = lane & 7;           // 0..7
    const int grp = lane >> 3;          // 0..3
    const int warp = threadIdx.x >> 5;
    const int gw = blockIdx.x * 16 + warp;      // 2368 warps
    const float4* __restrict__ h4 = (const float4*)h;

    const int c0 = sub, c1 = sub + 8, c2 = sub + 16;
    float4 bv0 = ((const float4*)b)[c0];
    float4 bv1 = ((const float4*)b)[c1];
    float4 bv2 = ((const float4*)b)[c2];

    for (int nb = gw * 4; nb < NN; nb += NB * 16 * 4) {
        const int node = nb + grp;
        const bool valid = (node < NN);
        const int beg = valid ? __ldcg(&g_rowptr[node]) : 0;
        const int end = valid ? __ldcg(&g_rowptr[node + 1]) : 0;

        float4 a0 = make_float4(0.f, 0.f, 0.f, 0.f);
        float4 a1 = make_float4(0.f, 0.f, 0.f, 0.f);
        float4 a2 = make_float4(0.f, 0.f, 0.f, 0.f);

        int e = beg;
        for (; e + 4 <= end; e += 4) {
            int2 E[4];
#pragma unroll
            for (int j = 0; j < 4; j++) E[j] = __ldcg(&g_edge[e + j]);
            float4 v0[4], v1[4], v2[4];
#pragma unroll
            for (int j = 0; j < 4; j++) {
                const float4* r = h4 + (size_t)E[j].x * 24;
                v0[j] = __ldcg(r + c0);
                v1[j] = __ldcg(r + c1);
                v2[j] = __ldcg(r + c2);
            }
#pragma unroll
            for (int j = 0; j < 4; j++) {
                float w = __int_as_float(E[j].y);
                a0.x += v0[j].x * w; a0.y += v0[j].y * w;
                a0.z += v0[j].z * w; a0.w += v0[j].w * w;
                a1.x += v1[j].x * w; a1.y += v1[j].y * w;
                a1.z += v1[j].z * w; a1.w += v1[j].w * w;
                a2.x += v2[j].x * w; a2.y += v2[j].y * w;
                a2.z += v2[j].z * w; a2.w += v2[j].w * w;
            }
        }
        for (; e < end; e++) {
            int2 E = __ldcg(&g_edge[e]);
            const float4* r = h4 + (size_t)E.x * 24;
            float4 v0 = __ldcg(r + c0);
            float4 v1 = __ldcg(r + c1);
            float4 v2 = __ldcg(r + c2);
            float w = __int_as_float(E.y);
            a0.x += v0.x * w; a0.y += v0.y * w; a0.z += v0.z * w; a0.w += v0.w * w;
            a1.x += v1.x * w; a1.y += v1.y * w; a1.z += v1.z * w; a1.w += v1.w * w;
            a2.x += v2.x * w; a2.y += v2.y * w; a2.z += v2.z * w; a2.w += v2.w * w;
        }

        if (valid) {
            const float dii = 1.0f / (float)(__ldcg(&g_cnt[node]) + 1);
            const float4* r = h4 + (size_t)node * 24;
            float4 h0 = __ldcg(r + c0);
            float4 h1 = __ldcg(r + c1);
            float4 h2 = __ldcg(r + c2);
            a0.x += h0.x * dii + bv0.x; a0.y += h0.y * dii + bv0.y;
            a0.z += h0.z * dii + bv0.z; a0.w += h0.w * dii + bv0.w;
            a1.x += h1.x * dii + bv1.x; a1.y += h1.y * dii + bv1.y;
            a1.z += h1.z * dii + bv1.z; a1.w += h1.w * dii + bv1.w;
            a2.x += h2.x * dii + bv2.x; a2.y += h2.y * dii + bv2.y;
            a2.z += h2.z * dii + bv2.z; a2.w += h2.w * dii + bv2.w;
            if (relu) {
                a0.x = fmaxf(a0.x, 0.f); a0.y = fmaxf(a0.y, 0.f);
                a0.z = fmaxf(a0.z, 0.f); a0.w = fmaxf(a0.w, 0.f);
                a1.x = fmaxf(a1.x, 0.f); a1.y = fmaxf(a1.y, 0.f);
                a1.z = fmaxf(a1.z, 0.f); a1.w = fmaxf(a1.w, 0.f);
                a2.x = fmaxf(a2.x, 0.f); a2.y = fmaxf(a2.y, 0.f);
                a2.z = fmaxf(a2.z, 0.f); a2.w = fmaxf(a2.w, 0.f);
            }
            float4* o = (float4*)out + (size_t)node * 24;
            o[c0] = a0; o[c1] = a1; o[c2] = a2;
        }
    }
}

// ---------------- the one persistent kernel --------------------------------
__global__ __launch_bounds__(NT, 1) void gcn_mega_kernel(
    const float* __restrict__ x, const int* __restrict__ ei,
    const float* __restrict__ W1, const float* __restrict__ b1,
    const float* __restrict__ W2, const float* __restrict__ b2,
    const float* __restrict__ W3, const float* __restrict__ b3,
    const float* __restrict__ W4, const float* __restrict__ b4,
    float* __restrict__ out)
{
    __shared__ float Xs[2][TM][33];     // per-half X tiles
    __shared__ float Ws[32][96];        // shared W chunk
    int* sc = (int*)Ws;                 // scan scratch (NT ints)

    const int tid = threadIdx.x;
    const int gtid = blockIdx.x * NT + tid;

    // P0: zero cnt + cursor
    for (int i = gtid; i < NN; i += GSZ) { g_cnt[i] = 0; g_cursor[i] = 0; }
    grid_barrier();

    // P1: degree count
    for (int e = gtid; e < NE; e += GSZ) atomicAdd(&g_cnt[ei[NE + e]], 1);
    grid_barrier();

    // P2a: per-thread element + block exclusive scan (CHUNK=338 <= NT)
    const int base = blockIdx.x * CHUNK;
    const int lim = min(base + CHUNK, NN);
    const int myi = base + tid;
    int mysum = (myi < lim) ? __ldcg(&g_cnt[myi]) : 0;
    sc[tid] = mysum;
    __syncthreads();
    for (int off = 1; off < NT; off <<= 1) {
        int v = (tid >= off) ? sc[tid - off] : 0;
        __syncthreads();
        sc[tid] += v;
        __syncthreads();
    }
    int myexcl = sc[tid] - mysum;
    if (tid == NT - 1) g_bsum[blockIdx.x] = sc[tid];
    grid_barrier();

    // P2b: warp-parallel exclusive scan of NB block sums (block 0, warp 0)
    if (blockIdx.x == 0 && tid < 32) {
        int carry = 0;
        for (int b0 = 0; b0 < NB; b0 += 32) {
            int i = b0 + tid;
            int v = (i < NB) ? __ldcg(&g_bsum[i]) : 0;
            int orig = v;
#pragma unroll
            for (int o = 1; o < 32; o <<= 1) {
                int t = __shfl_up_sync(0xffffffffu, v, o);
                if ((tid & 31) >= o) v += t;
            }
            if (i < NB) g_bsum[i] = carry + v - orig;   // exclusive
            carry += __shfl_sync(0xffffffffu, v, 31);
        }
        if (tid == 0) g_rowptr[NN] = carry;
    }
    grid_barrier();

    // P2c: final rowptr
    if (myi < lim) g_rowptr[myi] = __ldcg(&g_bsum[blockIdx.x]) + myexcl;
    grid_barrier();

    // P3: fill CSR with precomputed edge weight
    for (int e = gtid; e < NE; e += GSZ) {
        int s = ei[e];
        int d = ei[NE + e];
        float w = rsqrtf((float)((__ldcg(&g_cnt[s]) + 1) * (__ldcg(&g_cnt[d]) + 1)));
        int pos = atomicAdd(&g_cursor[d], 1);
        g_edge[__ldcg(&g_rowptr[d]) + pos] = make_int2(s, __float_as_int(w));
    }
    grid_barrier();

    // layers
    const float* gin[4] = { x, g_P, g_P, g_P };
    const float* gW[4]  = { W1, W2, W3, W4 };
    const float* gb[4]  = { b1, b2, b3, b4 };
    float*       gout[4] = { g_P, g_P, g_P, out };
    const int    gcin[4] = { 128, 96, 96, 96 };

    const int half = tid >> 8;          // 0 or 1
    for (int l = 0; l < 4; l++) {
        for (int p = blockIdx.x; p < NPAIRS; p += NB) {
            int tile = 2 * p + half;
            if (tile >= NTILES) tile = NTILES - 1;   // tail: duplicate write, benign
            gemm_tile(gin[l], gW[l], g_H, gcin[l], tile, Xs[half], Ws);
        }
        grid_barrier();
        gather_phase(g_H, gb[l], gout[l], (l < 3) ? 1 : 0);
        if (l < 3) grid_barrier();
    }
}

// ---------------- launch ----------------------------------------------------
extern "C" void kernel_launch(void* const* d_in, const int* in_sizes, int n_in,
                              void* d_out, int out_size) {
    const float* x  = (const float*)d_in[0];
    const int*   ei = (const int*)d_in[1];   // int32 (JAX demotes int64)
    const float* W1 = (const float*)d_in[2];
    const float* b1 = (const float*)d_in[3];
    const float* W2 = (const float*)d_in[4];
    const float* b2 = (const float*)d_in[5];
    const float* W3 = (const float*)d_in[6];
    const float* b3 = (const float*)d_in[7];
    const float* W4 = (const float*)d_in[8];
    const float* b4 = (const float*)d_in[9];
    float* out = (float*)d_out;

    gcn_mega_kernel<<<NB, NT>>>(x, ei, W1, b1, W2, b2, W3, b3, W4, b4, out);
}